// round 16
// baseline (speedup 1.0000x reference)
#include <cuda_runtime.h>
#include <cuda_bf16.h>
#include <math.h>
#include <cstdint>

// Problem constants
#define D_CH   2048
#define LSEQ   8192
#define NST    64
#define TCH    64      // chunk length for the scan
#define NCHUNK 128     // LSEQ / TCH

// ---------------- device scratch (static, no allocation) ----------------
__device__ float          g_dA[64 * 64];
__device__ float          g_inv[64 * 64];
__device__ __nv_bfloat16  g_dBhi[64 * 2048];     // dB n-major, bf16 hi
__device__ __nv_bfloat16  g_dBlo[64 * 2048];     // dB n-major, bf16 lo
__device__ __nv_bfloat16  g_Xhi[2048 * 8192];    // X bf16 hi, [d][t]
__device__ __nv_bfloat16  g_Xlo[2048 * 8192];    // X bf16 lo, [d][t]
__device__ float          g_Ut[8192 * 64];       // U: [t][n]
__device__ float          g_Ht[8192 * 64];       // H: [t][n]
__device__ float          g_esum[NCHUNK * 64];
__device__ float          g_hstart[NCHUNK * 64];
__device__ float          g_delta;

// ---------------- packed fp32x2 helpers ----------------
__device__ __forceinline__ unsigned long long splat2(float x) {
    unsigned long long r;
    asm("mov.b64 %0, {%1, %1};" : "=l"(r) : "r"(__float_as_uint(x)));
    return r;
}
__device__ __forceinline__ unsigned long long pack2(float x, float y) {
    unsigned long long r;
    asm("mov.b64 %0, {%1, %2};" : "=l"(r) : "r"(__float_as_uint(x)), "r"(__float_as_uint(y)));
    return r;
}
__device__ __forceinline__ void fma2(unsigned long long& d,
                                     unsigned long long a, unsigned long long b) {
    asm("fma.rn.f32x2 %0, %1, %2, %0;" : "+l"(d) : "l"(a), "l"(b));
}
__device__ __forceinline__ unsigned long long add2(unsigned long long a,
                                                   unsigned long long b) {
    unsigned long long r;
    asm("add.rn.f32x2 %0, %1, %2;" : "=l"(r) : "l"(a), "l"(b));
    return r;
}
__device__ __forceinline__ float2 unpk(unsigned long long v) {
    float2 f;
    asm("mov.b64 {%0, %1}, %2;" : "=f"(f.x), "=f"(f.y) : "l"(v));
    return f;
}
#define BAR64() asm volatile("bar.sync 1, 64;" ::: "memory")

// ---------------- mma.sync / ldmatrix / cp.async helpers (base-arch) ----------------
__device__ __forceinline__ uint32_t smem_u32(const void* p) {
    uint32_t a;
    asm("{ .reg .u64 t; cvta.to.shared.u64 t, %1; cvt.u32.u64 %0, t; }" : "=r"(a) : "l"(p));
    return a;
}
__device__ __forceinline__ void ldsm_x4(uint32_t* r, uint32_t addr) {
    asm volatile("ldmatrix.sync.aligned.m8n8.x4.shared.b16 {%0,%1,%2,%3}, [%4];"
                 : "=r"(r[0]), "=r"(r[1]), "=r"(r[2]), "=r"(r[3]) : "r"(addr));
}
__device__ __forceinline__ void ldsm_x4_t(uint32_t* r, uint32_t addr) {
    asm volatile("ldmatrix.sync.aligned.m8n8.x4.trans.shared.b16 {%0,%1,%2,%3}, [%4];"
                 : "=r"(r[0]), "=r"(r[1]), "=r"(r[2]), "=r"(r[3]) : "r"(addr));
}
__device__ __forceinline__ void mma16816(float* c, const uint32_t* a, const uint32_t* b) {
    asm volatile("mma.sync.aligned.m16n8k16.row.col.f32.bf16.bf16.f32 "
                 "{%0,%1,%2,%3}, {%4,%5,%6,%7}, {%8,%9}, {%0,%1,%2,%3};"
                 : "+f"(c[0]), "+f"(c[1]), "+f"(c[2]), "+f"(c[3])
                 : "r"(a[0]), "r"(a[1]), "r"(a[2]), "r"(a[3]), "r"(b[0]), "r"(b[1]));
}
__device__ __forceinline__ void cpa16(uint32_t dst, const void* src) {
    asm volatile("cp.async.cg.shared.global [%0], [%1], 16;" :: "r"(dst), "l"(src) : "memory");
}
#define CPA_COMMIT() asm volatile("cp.async.commit_group;" ::: "memory")
#define CPA_WAIT1()  asm volatile("cp.async.wait_group 1;" ::: "memory")
#define CPA_WAIT0()  asm volatile("cp.async.wait_group 0;" ::: "memory")

// ---------------- 1) prep: fp64 in-place Gauss-Jordan inverse in SMEM ----------------
__global__ __launch_bounds__(256) void prep_kernel(const float* __restrict__ A,
                                                   const float* __restrict__ logd)
{
    __shared__ double sM[64 * 65];
    __shared__ double fac_s[64];
    int tid = threadIdx.x;
    double delta = exp((double)logd[0]);

    for (int idx = tid; idx < 4096; idx += 256) {
        int i = idx >> 6, j = idx & 63;
        sM[i * 65 + j] = (i == j ? 1.0 : 0.0) - 0.5 * delta * (double)A[idx];
    }
    __syncthreads();

    for (int k = 0; k < 64; k++) {
        if (tid < 64) fac_s[tid] = sM[tid * 65 + k];
        __syncthreads();
        double piv = 1.0 / fac_s[k];
        if (tid < 64) sM[k * 65 + tid] = (tid == k) ? piv : sM[k * 65 + tid] * piv;
        __syncthreads();
        int i = tid & 63, jg = tid >> 6;
        if (i != k) {
            double f = fac_s[i];
#pragma unroll
            for (int q = 0; q < 16; q++) {
                int j = jg * 16 + q;
                double cur = sM[i * 65 + j];
                sM[i * 65 + j] = (j == k) ? (-f * piv) : (cur - f * sM[k * 65 + j]);
            }
        }
        __syncthreads();
    }

    for (int idx = tid; idx < 4096; idx += 256) {
        int i = idx >> 6, j = idx & 63;
        double minv = sM[i * 65 + j];
        g_inv[idx] = (float)minv;
        g_dA[idx]  = (float)(2.0 * minv - (i == j ? 1.0 : 0.0));
    }
    if (tid == 0) g_delta = (float)delta;
}

// ---------------- 2) dB (n-major, bf16 hi/lo split) ----------------
__global__ __launch_bounds__(256) void dB_kernel(const float* __restrict__ B)
{
    __shared__ float inv_s[64 * 64];
    int tid = threadIdx.x;
    for (int idx = tid; idx < 4096; idx += 256) inv_s[idx] = g_inv[idx];
    __syncthreads();

    float delta = g_delta;
    int d  = blockIdx.x * 64 + (tid & 63);
    int n0 = (tid >> 6) * 16;

    float acc[16];
#pragma unroll
    for (int q = 0; q < 16; q++) acc[q] = 0.f;

    for (int k = 0; k < 64; k++) {
        float b = B[k * 2048 + d];
#pragma unroll
        for (int q = 0; q < 16; q++) acc[q] += inv_s[(n0 + q) * 64 + k] * b;
    }
#pragma unroll
    for (int q = 0; q < 16; q++) {
        float v = delta * acc[q];
        __nv_bfloat16 hi = __float2bfloat16(v);
        __nv_bfloat16 lo = __float2bfloat16(v - __bfloat162float(hi));
        g_dBhi[(n0 + q) * 2048 + d] = hi;
        g_dBlo[(n0 + q) * 2048 + d] = lo;
    }
}

// ---------------- 2b) X split: fp32 -> bf16 hi/lo (bandwidth-bound) ----------------
__global__ __launch_bounds__(256) void xsplit_kernel(const float* __restrict__ X)
{
    size_t i = ((size_t)blockIdx.x * 256 + threadIdx.x) * 8;   // 8 elements per thread
    float4 x0 = *(const float4*)(X + i);
    float4 x1 = *(const float4*)(X + i + 4);
    float xs[8] = {x0.x, x0.y, x0.z, x0.w, x1.x, x1.y, x1.z, x1.w};
    uint32_t h[4], l[4];
#pragma unroll
    for (int q = 0; q < 4; q++) {
        __nv_bfloat16 h0 = __float2bfloat16(xs[2 * q]);
        __nv_bfloat16 h1 = __float2bfloat16(xs[2 * q + 1]);
        __nv_bfloat16 l0 = __float2bfloat16(xs[2 * q]     - __bfloat162float(h0));
        __nv_bfloat16 l1 = __float2bfloat16(xs[2 * q + 1] - __bfloat162float(h1));
        h[q] = (uint32_t)__bfloat16_as_ushort(h0) | ((uint32_t)__bfloat16_as_ushort(h1) << 16);
        l[q] = (uint32_t)__bfloat16_as_ushort(l0) | ((uint32_t)__bfloat16_as_ushort(l1) << 16);
    }
    *(uint4*)((char*)g_Xhi + i * 2) = make_uint4(h[0], h[1], h[2], h[3]);
    *(uint4*)((char*)g_Xlo + i * 2) = make_uint4(l[0], l[1], l[2], l[3]);
}

// ---------------- 3) GEMM1 via mma.sync bf16x3: Ut[t][n] = (dB @ X)^T ----------------
// Grid 64: CTA owns 128 t x 64 n. K=2048 in 32 chunks of 64, cp.async double-buffered.
// smem per buffer: sXhi/sXlo [64 k][128 t] stride 136 elem (272B), sBhi/sBlo [64 n][64 k]
// stride 72 elem (144B). Both strides are odd multiples of 16B -> ldmatrix conflict-free.
#define XSTRIDE 272        // bytes per k-row (136 bf16)
#define BSTRIDE 144        // bytes per n-row (72 bf16)
#define OFF_XH  0
#define OFF_XL  17408
#define OFF_BH  34816
#define OFF_BL  44032
#define BUFSZ   53248
#define G1_SMEM (2 * BUFSZ)

__device__ __forceinline__ void g1_issue(uint32_t sb, int buf, int t0, int k0, int tid)
{
    uint32_t base = sb + buf * BUFSZ;
#pragma unroll
    for (int f = tid; f < 1024; f += 256) {
        int k = f >> 4, c = f & 15;
        uint32_t doff = k * XSTRIDE + c * 16;
        const char* s = (const char*)g_Xhi + ((size_t)(k0 + k) * 8192 + t0 + c * 8) * 2;
        cpa16(base + OFF_XH + doff, s);
        cpa16(base + OFF_XL + doff, (const char*)g_Xlo + ((size_t)(k0 + k) * 8192 + t0 + c * 8) * 2);
    }
#pragma unroll
    for (int f = tid; f < 512; f += 256) {
        int n = f >> 3, c = f & 7;
        uint32_t doff = n * BSTRIDE + c * 16;
        cpa16(base + OFF_BH + doff, (const char*)g_dBhi + ((size_t)n * 2048 + k0 + c * 8) * 2);
        cpa16(base + OFF_BL + doff, (const char*)g_dBlo + ((size_t)n * 2048 + k0 + c * 8) * 2);
    }
    CPA_COMMIT();
}

__global__ __launch_bounds__(256) void gemm1_mma(const float* __restrict__ Xunused)
{
    extern __shared__ __align__(1024) char smem[];
    uint32_t sb = smem_u32(smem);
    int tid = threadIdx.x, lane = tid & 31, wid = tid >> 5;
    int t0 = blockIdx.x * 128;
    int mw = wid & 3;        // t quarter (32 t)
    int nw = wid >> 2;       // n half (32 n)

    // ldmatrix address components (element units unless noted)
    int a_krow = (lane & 7) + ((lane >> 4) << 3);       // + ks
    int a_tcol = mw * 32 + (lane & 8);                  // + mt*16
    int b_nrow = nw * 32 + ((lane >> 4) << 3) + (lane & 7);  // + p*16
    int b_kcol = lane & 8;                              // + ks

    float acc[2][4][4];
#pragma unroll
    for (int mt = 0; mt < 2; mt++)
#pragma unroll
        for (int nt = 0; nt < 4; nt++)
#pragma unroll
            for (int q = 0; q < 4; q++) acc[mt][nt][q] = 0.f;

    g1_issue(sb, 0, t0, 0, tid);

    for (int it = 0; it < 32; it++) {
        int b = it & 1;
        if (it + 1 < 32) {
            g1_issue(sb, 1 - b, t0, (it + 1) * 64, tid);
            CPA_WAIT1();
        } else {
            CPA_WAIT0();
        }
        __syncthreads();

        uint32_t xh = sb + b * BUFSZ + OFF_XH;
        uint32_t xl = sb + b * BUFSZ + OFF_XL;
        uint32_t bh = sb + b * BUFSZ + OFF_BH;
        uint32_t bl = sb + b * BUFSZ + OFF_BL;

#pragma unroll
        for (int s = 0; s < 4; s++) {
            int ks = s * 16;
            uint32_t aH[2][4], aL[2][4], bH[2][4], bL[2][4];
#pragma unroll
            for (int mt = 0; mt < 2; mt++) {
                uint32_t ao = (uint32_t)(ks + a_krow) * XSTRIDE + (a_tcol + mt * 16) * 2;
                ldsm_x4_t(aH[mt], xh + ao);
                ldsm_x4_t(aL[mt], xl + ao);
            }
#pragma unroll
            for (int p = 0; p < 2; p++) {
                uint32_t bo = (uint32_t)(b_nrow + p * 16) * BSTRIDE + (ks + b_kcol) * 2;
                ldsm_x4(bH[p], bh + bo);
                ldsm_x4(bL[p], bl + bo);
            }
#pragma unroll
            for (int mt = 0; mt < 2; mt++)
#pragma unroll
                for (int nt = 0; nt < 4; nt++) {
                    const uint32_t* bhp = &bH[nt >> 1][(nt & 1) * 2];
                    const uint32_t* blp = &bL[nt >> 1][(nt & 1) * 2];
                    mma16816(acc[mt][nt], aH[mt], bhp);
                    mma16816(acc[mt][nt], aH[mt], blp);
                    mma16816(acc[mt][nt], aL[mt], bhp);
                }
        }
        __syncthreads();
    }

    // epilogue: thread holds c(m=lane>>2, n=(lane&3)*2) and (m+8, n)
#pragma unroll
    for (int mt = 0; mt < 2; mt++)
#pragma unroll
        for (int nt = 0; nt < 4; nt++) {
            int t = t0 + mw * 32 + mt * 16 + (lane >> 2);
            int n = nw * 32 + nt * 8 + (lane & 3) * 2;
            *(float2*)(g_Ut + (size_t)t * 64 + n)       = make_float2(acc[mt][nt][0], acc[mt][nt][1]);
            *(float2*)(g_Ut + (size_t)(t + 8) * 64 + n) = make_float2(acc[mt][nt][2], acc[mt][nt][3]);
        }
}

// ---------------- 4a) pass A: register-row local scans (h0 = 0) ----------------
__global__ __launch_bounds__(256) void scan_passA()
{
    __shared__ __align__(16) float u_s[64 * 64];
    __shared__ __align__(16) float hb[2][64];
    int tid = threadIdx.x, c = blockIdx.x;

    for (int f = tid; f < 1024; f += 256)
        ((float4*)u_s)[f] = ((const float4*)(g_Ut + c * 4096))[f];
    if (tid < 64) hb[0][tid] = 0.f;
    __syncthreads();
    if (tid >= 64) return;

    unsigned long long a[32];
    const float4* rowp = (const float4*)(g_dA + tid * 64);
#pragma unroll
    for (int q = 0; q < 16; q++) {
        float4 v = rowp[q];
        a[2 * q]     = pack2(v.x, v.y);
        a[2 * q + 1] = pack2(v.z, v.w);
    }

    float h = 0.f;
    for (int j = 0; j < TCH; j++) {
        const unsigned long long* hp = (const unsigned long long*)hb[j & 1];
        unsigned long long acc0 = 0, acc1 = 0, acc2 = 0, acc3 = 0;
#pragma unroll
        for (int q = 0; q < 8; q++) {
            fma2(acc0, a[4 * q + 0], hp[4 * q + 0]);
            fma2(acc1, a[4 * q + 1], hp[4 * q + 1]);
            fma2(acc2, a[4 * q + 2], hp[4 * q + 2]);
            fma2(acc3, a[4 * q + 3], hp[4 * q + 3]);
        }
        float2 f = unpk(add2(add2(acc0, acc1), add2(acc2, acc3)));
        h = f.x + f.y + u_s[j * 64 + tid];
        hb[(j + 1) & 1][tid] = h;
        BAR64();
    }
    g_esum[c * 64 + tid] = h;
}

// ---------------- 4b) pass B: dA^64 via squaring + register-row combine ----------------
__global__ __launch_bounds__(256) void scan_passB()
{
    __shared__ __align__(16) float buf0[64 * 64];
    __shared__ __align__(16) float buf1[64 * 64];
    __shared__ __align__(16) float hb[2][64];
    int tid = threadIdx.x;

    for (int idx = tid; idx < 4096; idx += 256) buf0[idx] = g_dA[idx];
    __syncthreads();

    float* in  = buf0;
    float* out = buf1;
    int ty = tid >> 4, tx = tid & 15;

    for (int s = 0; s < 6; s++) {
        float acc[4][4];
#pragma unroll
        for (int r = 0; r < 4; r++)
#pragma unroll
            for (int j = 0; j < 4; j++) acc[r][j] = 0.f;
        for (int k = 0; k < 64; k++) {
            float bv[4];
#pragma unroll
            for (int j = 0; j < 4; j++) bv[j] = in[k * 64 + tx * 4 + j];
#pragma unroll
            for (int r = 0; r < 4; r++) {
                float av = in[(ty * 4 + r) * 64 + k];
#pragma unroll
                for (int j = 0; j < 4; j++) acc[r][j] += av * bv[j];
            }
        }
#pragma unroll
        for (int r = 0; r < 4; r++)
#pragma unroll
            for (int j = 0; j < 4; j++)
                out[(ty * 4 + r) * 64 + tx * 4 + j] = acc[r][j];
        __syncthreads();
        float* tmp = in; in = out; out = tmp;
    }

    if (tid >= 64) return;

    unsigned long long a[32];
#pragma unroll
    for (int q = 0; q < 16; q++) {
        float4 v = *(const float4*)(in + tid * 64 + q * 4);
        a[2 * q]     = pack2(v.x, v.y);
        a[2 * q + 1] = pack2(v.z, v.w);
    }

    float e0 = g_esum[tid];
    float e1 = g_esum[64 + tid];
    float h = 0.f;
    hb[0][tid] = 0.f;
    BAR64();

    for (int c = 0; c < NCHUNK; c++) {
        g_hstart[c * 64 + tid] = h;
        float en = (c + 2 < NCHUNK) ? __ldg(g_esum + (c + 2) * 64 + tid) : 0.f;
        const unsigned long long* hp = (const unsigned long long*)hb[c & 1];
        unsigned long long acc0 = 0, acc1 = 0, acc2 = 0, acc3 = 0;
#pragma unroll
        for (int q = 0; q < 8; q++) {
            fma2(acc0, a[4 * q + 0], hp[4 * q + 0]);
            fma2(acc1, a[4 * q + 1], hp[4 * q + 1]);
            fma2(acc2, a[4 * q + 2], hp[4 * q + 2]);
            fma2(acc3, a[4 * q + 3], hp[4 * q + 3]);
        }
        float2 f = unpk(add2(add2(acc0, acc1), add2(acc2, acc3)));
        h = f.x + f.y + e0;
        e0 = e1; e1 = en;
        hb[(c + 1) & 1][tid] = h;
        BAR64();
    }
}

// ---------------- 4c) pass C: local scans with correct h0, write H ----------------
__global__ __launch_bounds__(256) void scan_passC()
{
    __shared__ __align__(16) float u_s[64 * 64];
    __shared__ __align__(16) float hb[2][64];
    int tid = threadIdx.x, c = blockIdx.x;

    for (int f = tid; f < 1024; f += 256)
        ((float4*)u_s)[f] = ((const float4*)(g_Ut + c * 4096))[f];
    if (tid < 64) hb[0][tid] = g_hstart[c * 64 + tid];
    __syncthreads();
    if (tid >= 64) return;

    unsigned long long a[32];
    const float4* rowp = (const float4*)(g_dA + tid * 64);
#pragma unroll
    for (int q = 0; q < 16; q++) {
        float4 v = rowp[q];
        a[2 * q]     = pack2(v.x, v.y);
        a[2 * q + 1] = pack2(v.z, v.w);
    }

    for (int j = 0; j < TCH; j++) {
        const unsigned long long* hp = (const unsigned long long*)hb[j & 1];
        unsigned long long acc0 = 0, acc1 = 0, acc2 = 0, acc3 = 0;
#pragma unroll
        for (int q = 0; q < 8; q++) {
            fma2(acc0, a[4 * q + 0], hp[4 * q + 0]);
            fma2(acc1, a[4 * q + 1], hp[4 * q + 1]);
            fma2(acc2, a[4 * q + 2], hp[4 * q + 2]);
            fma2(acc3, a[4 * q + 3], hp[4 * q + 3]);
        }
        float2 f = unpk(add2(add2(acc0, acc1), add2(acc2, acc3)));
        float h = f.x + f.y + u_s[j * 64 + tid];
        u_s[j * 64 + tid] = h;
        hb[(j + 1) & 1][tid] = h;
        BAR64();
    }

    float4* dst = (float4*)(g_Ht + c * 4096);
#pragma unroll
    for (int q = 0; q < 16; q++)
        dst[q * 64 + tid] = ((const float4*)u_s)[q * 64 + tid];
}

// ---------------- 5) GEMM2: Y = C @ H + Dp * X, 128x128 tiles, f32x2 ----------------
__global__ __launch_bounds__(256) void gemm2_kernel(const float* __restrict__ X,
                                                    const float* __restrict__ C,
                                                    const float* __restrict__ Dp,
                                                    float* __restrict__ Y)
{
    __shared__ __align__(16) float sC[32 * 136];
    __shared__ __align__(16) float sH[32 * 136];
    int tid = threadIdx.x;
    int t0 = blockIdx.x * 128, d0 = blockIdx.y * 128;
    int tx = tid & 15;
    int ty = tid >> 4;

    unsigned long long acc[8][4];
#pragma unroll
    for (int r = 0; r < 8; r++)
#pragma unroll
        for (int c = 0; c < 4; c++) acc[r][c] = 0ull;

    for (int kb = 0; kb < 64; kb += 32) {
        for (int idx = tid; idx < 4096; idx += 256) {
            int dd = idx >> 5, k = idx & 31;
            sC[k * 136 + dd] = C[(d0 + dd) * 64 + kb + k];
            sH[k * 136 + dd] = g_Ht[(size_t)(t0 + dd) * 64 + kb + k];
        }
        __syncthreads();

#pragma unroll 4
        for (int k = 0; k < 32; k++) {
            float4 a0 = *(const float4*)(sC + k * 136 + ty * 8);
            float4 a1 = *(const float4*)(sC + k * 136 + ty * 8 + 4);
            ulonglong2 b01 = *(const ulonglong2*)(sH + k * 136 + tx * 8);
            ulonglong2 b23 = *(const ulonglong2*)(sH + k * 136 + tx * 8 + 4);
            unsigned long long bv[4] = {b01.x, b01.y, b23.x, b23.y};
            unsigned long long pa[8];
            pa[0] = splat2(a0.x); pa[1] = splat2(a0.y);
            pa[2] = splat2(a0.z); pa[3] = splat2(a0.w);
            pa[4] = splat2(a1.x); pa[5] = splat2(a1.y);
            pa[6] = splat2(a1.z); pa[7] = splat2(a1.w);
#pragma unroll
            for (int r = 0; r < 8; r++)
#pragma unroll
                for (int c = 0; c < 4; c++) fma2(acc[r][c], pa[r], bv[c]);
        }
        __syncthreads();
    }

#pragma unroll
    for (int r = 0; r < 8; r++) {
        int d = d0 + ty * 8 + r;
        float dp = Dp[d];
        const float4 x0 = *(const float4*)(X + (size_t)d * LSEQ + t0 + tx * 8);
        const float4 x1 = *(const float4*)(X + (size_t)d * LSEQ + t0 + tx * 8 + 4);
        float2 p0 = unpk(acc[r][0]);
        float2 p1 = unpk(acc[r][1]);
        float2 p2 = unpk(acc[r][2]);
        float2 p3 = unpk(acc[r][3]);
        float4 o0 = make_float4(p0.x + dp * x0.x, p0.y + dp * x0.y,
                                p1.x + dp * x0.z, p1.y + dp * x0.w);
        float4 o1 = make_float4(p2.x + dp * x1.x, p2.y + dp * x1.y,
                                p3.x + dp * x1.z, p3.y + dp * x1.w);
        *(float4*)(Y + (size_t)d * LSEQ + t0 + tx * 8)     = o0;
        *(float4*)(Y + (size_t)d * LSEQ + t0 + tx * 8 + 4) = o1;
    }
}

// ---------------- launch ----------------
extern "C" void kernel_launch(void* const* d_in, const int* in_sizes, int n_in,
                              void* d_out, int out_size)
{
    const float* X    = (const float*)d_in[0];   // (2048, 8192)
    const float* A    = (const float*)d_in[1];   // (64, 64)
    const float* B    = (const float*)d_in[2];   // (64, 2048)
    const float* C    = (const float*)d_in[3];   // (2048, 64)
    const float* Dp   = (const float*)d_in[4];   // (2048,)
    const float* logd = (const float*)d_in[5];   // (1,)
    float* Y = (float*)d_out;                    // (2048, 8192)

    cudaFuncSetAttribute(gemm1_mma, cudaFuncAttributeMaxDynamicSharedMemorySize, G1_SMEM);

    prep_kernel<<<1, 256>>>(A, logd);
    dB_kernel<<<32, 256>>>(B);
    xsplit_kernel<<<8192, 256>>>(X);
    gemm1_mma<<<64, 256, G1_SMEM>>>(X);
    scan_passA<<<NCHUNK, 256>>>();
    scan_passB<<<1, 256>>>();
    scan_passC<<<NCHUNK, 256>>>();
    gemm2_kernel<<<dim3(LSEQ / 128, D_CH / 128), 256>>>(X, C, Dp, Y);
}

// round 17
// speedup vs baseline: 1.2028x; 1.2028x over previous
#include <cuda_runtime.h>
#include <cuda_bf16.h>
#include <math.h>
#include <cstdint>

// Problem constants
#define D_CH   2048
#define LSEQ   8192
#define NST    64
#define TCH    64      // chunk length for the scan
#define NCHUNK 128     // LSEQ / TCH

// ---------------- device scratch (static, no allocation) ----------------
__device__ float          g_dA[64 * 64];
__device__ float          g_inv[64 * 64];
__device__ __nv_bfloat16  g_dBhi[64 * 2048];     // dB n-major, bf16 hi
__device__ __nv_bfloat16  g_dBlo[64 * 2048];     // dB n-major, bf16 lo
__device__ __nv_bfloat16  g_Xhi[2048 * 8192];    // X bf16 hi, [d][t]
__device__ __nv_bfloat16  g_Xlo[2048 * 8192];    // X bf16 lo, [d][t]
__device__ __nv_bfloat16  g_Chi[2048 * 64];      // C bf16 hi, [d][k]
__device__ __nv_bfloat16  g_Clo[2048 * 64];      // C bf16 lo
__device__ __nv_bfloat16  g_Hthi[8192 * 64];     // H bf16 hi, [t][k]
__device__ __nv_bfloat16  g_Htlo[8192 * 64];     // H bf16 lo
__device__ float          g_U1p[2 * 8192 * 64];  // gemm1 k-split partials
__device__ float          g_Ut[8192 * 64];       // U: [t][n]
__device__ float          g_Ht[8192 * 64];       // H: [t][n] fp32
__device__ float          g_esum[NCHUNK * 64];
__device__ float          g_hstart[NCHUNK * 64];
__device__ float          g_delta;

// ---------------- packed fp32x2 helpers ----------------
__device__ __forceinline__ unsigned long long pack2(float x, float y) {
    unsigned long long r;
    asm("mov.b64 %0, {%1, %2};" : "=l"(r) : "r"(__float_as_uint(x)), "r"(__float_as_uint(y)));
    return r;
}
__device__ __forceinline__ void fma2(unsigned long long& d,
                                     unsigned long long a, unsigned long long b) {
    asm("fma.rn.f32x2 %0, %1, %2, %0;" : "+l"(d) : "l"(a), "l"(b));
}
__device__ __forceinline__ unsigned long long add2(unsigned long long a,
                                                   unsigned long long b) {
    unsigned long long r;
    asm("add.rn.f32x2 %0, %1, %2;" : "=l"(r) : "l"(a), "l"(b));
    return r;
}
__device__ __forceinline__ float2 unpk(unsigned long long v) {
    float2 f;
    asm("mov.b64 {%0, %1}, %2;" : "=f"(f.x), "=f"(f.y) : "l"(v));
    return f;
}
#define BAR64() asm volatile("bar.sync 1, 64;" ::: "memory")

// ---------------- mma.sync / ldmatrix / cp.async helpers (base-arch) ----------------
__device__ __forceinline__ uint32_t smem_u32(const void* p) {
    uint32_t a;
    asm("{ .reg .u64 t; cvta.to.shared.u64 t, %1; cvt.u32.u64 %0, t; }" : "=r"(a) : "l"(p));
    return a;
}
__device__ __forceinline__ void ldsm_x4(uint32_t* r, uint32_t addr) {
    asm volatile("ldmatrix.sync.aligned.m8n8.x4.shared.b16 {%0,%1,%2,%3}, [%4];"
                 : "=r"(r[0]), "=r"(r[1]), "=r"(r[2]), "=r"(r[3]) : "r"(addr));
}
__device__ __forceinline__ void ldsm_x4_t(uint32_t* r, uint32_t addr) {
    asm volatile("ldmatrix.sync.aligned.m8n8.x4.trans.shared.b16 {%0,%1,%2,%3}, [%4];"
                 : "=r"(r[0]), "=r"(r[1]), "=r"(r[2]), "=r"(r[3]) : "r"(addr));
}
__device__ __forceinline__ void mma16816(float* c, const uint32_t* a, const uint32_t* b) {
    asm volatile("mma.sync.aligned.m16n8k16.row.col.f32.bf16.bf16.f32 "
                 "{%0,%1,%2,%3}, {%4,%5,%6,%7}, {%8,%9}, {%0,%1,%2,%3};"
                 : "+f"(c[0]), "+f"(c[1]), "+f"(c[2]), "+f"(c[3])
                 : "r"(a[0]), "r"(a[1]), "r"(a[2]), "r"(a[3]), "r"(b[0]), "r"(b[1]));
}
__device__ __forceinline__ void cpa16(uint32_t dst, const void* src) {
    asm volatile("cp.async.cg.shared.global [%0], [%1], 16;" :: "r"(dst), "l"(src) : "memory");
}
#define CPA_COMMIT() asm volatile("cp.async.commit_group;" ::: "memory")
#define CPA_WAIT1()  asm volatile("cp.async.wait_group 1;" ::: "memory")
#define CPA_WAIT0()  asm volatile("cp.async.wait_group 0;" ::: "memory")

__device__ __forceinline__ uint32_t bfsplit2(float a, float b, uint32_t& lo) {
    __nv_bfloat16 h0 = __float2bfloat16(a);
    __nv_bfloat16 h1 = __float2bfloat16(b);
    __nv_bfloat16 l0 = __float2bfloat16(a - __bfloat162float(h0));
    __nv_bfloat16 l1 = __float2bfloat16(b - __bfloat162float(h1));
    lo = (uint32_t)__bfloat16_as_ushort(l0) | ((uint32_t)__bfloat16_as_ushort(l1) << 16);
    return (uint32_t)__bfloat16_as_ushort(h0) | ((uint32_t)__bfloat16_as_ushort(h1) << 16);
}

// ---------------- 1) prep: fp64 in-place Gauss-Jordan inverse in SMEM ----------------
__global__ __launch_bounds__(256) void prep_kernel(const float* __restrict__ A,
                                                   const float* __restrict__ logd)
{
    __shared__ double sM[64 * 65];
    __shared__ double fac_s[64];
    int tid = threadIdx.x;
    double delta = exp((double)logd[0]);

    for (int idx = tid; idx < 4096; idx += 256) {
        int i = idx >> 6, j = idx & 63;
        sM[i * 65 + j] = (i == j ? 1.0 : 0.0) - 0.5 * delta * (double)A[idx];
    }
    __syncthreads();

    for (int k = 0; k < 64; k++) {
        if (tid < 64) fac_s[tid] = sM[tid * 65 + k];
        __syncthreads();
        double piv = 1.0 / fac_s[k];
        if (tid < 64) sM[k * 65 + tid] = (tid == k) ? piv : sM[k * 65 + tid] * piv;
        __syncthreads();
        int i = tid & 63, jg = tid >> 6;
        if (i != k) {
            double f = fac_s[i];
#pragma unroll
            for (int q = 0; q < 16; q++) {
                int j = jg * 16 + q;
                double cur = sM[i * 65 + j];
                sM[i * 65 + j] = (j == k) ? (-f * piv) : (cur - f * sM[k * 65 + j]);
            }
        }
        __syncthreads();
    }

    for (int idx = tid; idx < 4096; idx += 256) {
        int i = idx >> 6, j = idx & 63;
        double minv = sM[i * 65 + j];
        g_inv[idx] = (float)minv;
        g_dA[idx]  = (float)(2.0 * minv - (i == j ? 1.0 : 0.0));
    }
    if (tid == 0) g_delta = (float)delta;
}

// ---------------- 2) dB (n-major, bf16 hi/lo split) ----------------
__global__ __launch_bounds__(256) void dB_kernel(const float* __restrict__ B)
{
    __shared__ float inv_s[64 * 64];
    int tid = threadIdx.x;
    for (int idx = tid; idx < 4096; idx += 256) inv_s[idx] = g_inv[idx];
    __syncthreads();

    float delta = g_delta;
    int d  = blockIdx.x * 64 + (tid & 63);
    int n0 = (tid >> 6) * 16;

    float acc[16];
#pragma unroll
    for (int q = 0; q < 16; q++) acc[q] = 0.f;

    for (int k = 0; k < 64; k++) {
        float b = B[k * 2048 + d];
#pragma unroll
        for (int q = 0; q < 16; q++) acc[q] += inv_s[(n0 + q) * 64 + k] * b;
    }
#pragma unroll
    for (int q = 0; q < 16; q++) {
        float v = delta * acc[q];
        __nv_bfloat16 hi = __float2bfloat16(v);
        __nv_bfloat16 lo = __float2bfloat16(v - __bfloat162float(hi));
        g_dBhi[(n0 + q) * 2048 + d] = hi;
        g_dBlo[(n0 + q) * 2048 + d] = lo;
    }
}

// ---------------- 2b) X split: fp32 -> bf16 hi/lo ----------------
__global__ __launch_bounds__(256) void xsplit_kernel(const float* __restrict__ X)
{
    size_t i = ((size_t)blockIdx.x * 256 + threadIdx.x) * 8;
    float4 x0 = *(const float4*)(X + i);
    float4 x1 = *(const float4*)(X + i + 4);
    uint4 h, l;
    h.x = bfsplit2(x0.x, x0.y, l.x);
    h.y = bfsplit2(x0.z, x0.w, l.y);
    h.z = bfsplit2(x1.x, x1.y, l.z);
    h.w = bfsplit2(x1.z, x1.w, l.w);
    *(uint4*)((char*)g_Xhi + i * 2) = h;
    *(uint4*)((char*)g_Xlo + i * 2) = l;
}

// ---------------- 2c) C split ----------------
__global__ __launch_bounds__(256) void csplit_kernel(const float* __restrict__ C)
{
    size_t i = ((size_t)blockIdx.x * 256 + threadIdx.x) * 4;   // 131072 elems, grid 128
    float4 v = *(const float4*)(C + i);
    uint2 h, l;
    h.x = bfsplit2(v.x, v.y, l.x);
    h.y = bfsplit2(v.z, v.w, l.y);
    *(uint2*)((char*)g_Chi + i * 2) = h;
    *(uint2*)((char*)g_Clo + i * 2) = l;
}

// ---------------- 2d) H split (after scan) ----------------
__global__ __launch_bounds__(256) void hsplit_kernel()
{
    size_t i = ((size_t)blockIdx.x * 256 + threadIdx.x) * 4;   // 524288 elems, grid 512
    float4 v = *(const float4*)(g_Ht + i);
    uint2 h, l;
    h.x = bfsplit2(v.x, v.y, l.x);
    h.y = bfsplit2(v.z, v.w, l.y);
    *(uint2*)((char*)g_Hthi + i * 2) = h;
    *(uint2*)((char*)g_Htlo + i * 2) = l;
}

// ---------------- 3) GEMM1 via mma.sync bf16x3, k-split x2 ----------------
#define XSTRIDE 272        // bytes per k-row (136 bf16)
#define BSTRIDE 144        // bytes per n-row (72 bf16)
#define OFF_XH  0
#define OFF_XL  17408
#define OFF_BH  34816
#define OFF_BL  44032
#define BUFSZ   53248
#define G1_SMEM (2 * BUFSZ)

__device__ __forceinline__ void g1_issue(uint32_t sb, int buf, int t0, int k0, int tid)
{
    uint32_t base = sb + buf * BUFSZ;
#pragma unroll
    for (int f = tid; f < 1024; f += 256) {
        int k = f >> 4, c = f & 15;
        uint32_t doff = k * XSTRIDE + c * 16;
        cpa16(base + OFF_XH + doff, (const char*)g_Xhi + ((size_t)(k0 + k) * 8192 + t0 + c * 8) * 2);
        cpa16(base + OFF_XL + doff, (const char*)g_Xlo + ((size_t)(k0 + k) * 8192 + t0 + c * 8) * 2);
    }
#pragma unroll
    for (int f = tid; f < 512; f += 256) {
        int n = f >> 3, c = f & 7;
        uint32_t doff = n * BSTRIDE + c * 16;
        cpa16(base + OFF_BH + doff, (const char*)g_dBhi + ((size_t)n * 2048 + k0 + c * 8) * 2);
        cpa16(base + OFF_BL + doff, (const char*)g_dBlo + ((size_t)n * 2048 + k0 + c * 8) * 2);
    }
    CPA_COMMIT();
}

__global__ __launch_bounds__(256) void gemm1_mma()
{
    extern __shared__ __align__(1024) char smem[];
    uint32_t sb = smem_u32(smem);
    int tid = threadIdx.x, lane = tid & 31, wid = tid >> 5;
    int t0 = blockIdx.x * 128;
    int kbase = blockIdx.y * 1024;
    int mw = wid & 3;        // t quarter (32 t)
    int nw = wid >> 2;       // n half (32 n)

    int a_krow = (lane & 7) + ((lane >> 4) << 3);
    int a_tcol = mw * 32 + (lane & 8);
    int b_nrow = nw * 32 + ((lane >> 4) << 3) + (lane & 7);
    int b_kcol = lane & 8;

    float acc[2][4][4];
#pragma unroll
    for (int mt = 0; mt < 2; mt++)
#pragma unroll
        for (int nt = 0; nt < 4; nt++)
#pragma unroll
            for (int q = 0; q < 4; q++) acc[mt][nt][q] = 0.f;

    g1_issue(sb, 0, t0, kbase, tid);

    for (int it = 0; it < 16; it++) {
        int b = it & 1;
        if (it + 1 < 16) {
            g1_issue(sb, 1 - b, t0, kbase + (it + 1) * 64, tid);
            CPA_WAIT1();
        } else {
            CPA_WAIT0();
        }
        __syncthreads();

        uint32_t xh = sb + b * BUFSZ + OFF_XH;
        uint32_t xl = sb + b * BUFSZ + OFF_XL;
        uint32_t bh = sb + b * BUFSZ + OFF_BH;
        uint32_t bl = sb + b * BUFSZ + OFF_BL;

#pragma unroll
        for (int s = 0; s < 4; s++) {
            int ks = s * 16;
            uint32_t aH[2][4], aL[2][4], bH[2][4], bL[2][4];
#pragma unroll
            for (int mt = 0; mt < 2; mt++) {
                uint32_t ao = (uint32_t)(ks + a_krow) * XSTRIDE + (a_tcol + mt * 16) * 2;
                ldsm_x4_t(aH[mt], xh + ao);
                ldsm_x4_t(aL[mt], xl + ao);
            }
#pragma unroll
            for (int p = 0; p < 2; p++) {
                uint32_t bo = (uint32_t)(b_nrow + p * 16) * BSTRIDE + (ks + b_kcol) * 2;
                ldsm_x4(bH[p], bh + bo);
                ldsm_x4(bL[p], bl + bo);
            }
#pragma unroll
            for (int mt = 0; mt < 2; mt++)
#pragma unroll
                for (int nt = 0; nt < 4; nt++) {
                    const uint32_t* bhp = &bH[nt >> 1][(nt & 1) * 2];
                    const uint32_t* blp = &bL[nt >> 1][(nt & 1) * 2];
                    mma16816(acc[mt][nt], aH[mt], bhp);
                    mma16816(acc[mt][nt], aH[mt], blp);
                    mma16816(acc[mt][nt], aL[mt], bhp);
                }
        }
        __syncthreads();
    }

    float* dstb = g_U1p + (size_t)blockIdx.y * (8192 * 64);
#pragma unroll
    for (int mt = 0; mt < 2; mt++)
#pragma unroll
        for (int nt = 0; nt < 4; nt++) {
            int t = t0 + mw * 32 + mt * 16 + (lane >> 2);
            int n = nw * 32 + nt * 8 + (lane & 3) * 2;
            *(float2*)(dstb + (size_t)t * 64 + n)       = make_float2(acc[mt][nt][0], acc[mt][nt][1]);
            *(float2*)(dstb + (size_t)(t + 8) * 64 + n) = make_float2(acc[mt][nt][2], acc[mt][nt][3]);
        }
}

// ---------------- 3b) reduce the 2 k-split partials ----------------
__global__ __launch_bounds__(256) void g1reduce_kernel()
{
    int f = blockIdx.x * 256 + threadIdx.x;    // 131072 float4
    const float4* p0 = (const float4*)g_U1p;
    const float4* p1 = (const float4*)(g_U1p + 8192 * 64);
    float4 a = p0[f], b = p1[f];
    ((float4*)g_Ut)[f] = make_float4(a.x + b.x, a.y + b.y, a.z + b.z, a.w + b.w);
}

// ---------------- 4a) pass A: register-row local scans (h0 = 0) ----------------
__global__ __launch_bounds__(256) void scan_passA()
{
    __shared__ __align__(16) float u_s[64 * 64];
    __shared__ __align__(16) float hb[2][64];
    int tid = threadIdx.x, c = blockIdx.x;

    for (int f = tid; f < 1024; f += 256)
        ((float4*)u_s)[f] = ((const float4*)(g_Ut + c * 4096))[f];
    if (tid < 64) hb[0][tid] = 0.f;
    __syncthreads();
    if (tid >= 64) return;

    unsigned long long a[32];
    const float4* rowp = (const float4*)(g_dA + tid * 64);
#pragma unroll
    for (int q = 0; q < 16; q++) {
        float4 v = rowp[q];
        a[2 * q]     = pack2(v.x, v.y);
        a[2 * q + 1] = pack2(v.z, v.w);
    }

    float h = 0.f;
    for (int j = 0; j < TCH; j++) {
        const unsigned long long* hp = (const unsigned long long*)hb[j & 1];
        unsigned long long acc0 = 0, acc1 = 0, acc2 = 0, acc3 = 0;
#pragma unroll
        for (int q = 0; q < 8; q++) {
            fma2(acc0, a[4 * q + 0], hp[4 * q + 0]);
            fma2(acc1, a[4 * q + 1], hp[4 * q + 1]);
            fma2(acc2, a[4 * q + 2], hp[4 * q + 2]);
            fma2(acc3, a[4 * q + 3], hp[4 * q + 3]);
        }
        float2 f = unpk(add2(add2(acc0, acc1), add2(acc2, acc3)));
        h = f.x + f.y + u_s[j * 64 + tid];
        hb[(j + 1) & 1][tid] = h;
        BAR64();
    }
    g_esum[c * 64 + tid] = h;
}

// ---------------- 4b) pass B: dA^64 via squaring + register-row combine ----------------
__global__ __launch_bounds__(256) void scan_passB()
{
    __shared__ __align__(16) float buf0[64 * 64];
    __shared__ __align__(16) float buf1[64 * 64];
    __shared__ __align__(16) float hb[2][64];
    int tid = threadIdx.x;

    for (int idx = tid; idx < 4096; idx += 256) buf0[idx] = g_dA[idx];
    __syncthreads();

    float* in  = buf0;
    float* out = buf1;
    int ty = tid >> 4, tx = tid & 15;

    for (int s = 0; s < 6; s++) {
        float acc[4][4];
#pragma unroll
        for (int r = 0; r < 4; r++)
#pragma unroll
            for (int j = 0; j < 4; j++) acc[r][j] = 0.f;
        for (int k = 0; k < 64; k++) {
            float bv[4];
#pragma unroll
            for (int j = 0; j < 4; j++) bv[j] = in[k * 64 + tx * 4 + j];
#pragma unroll
            for (int r = 0; r < 4; r++) {
                float av = in[(ty * 4 + r) * 64 + k];
#pragma unroll
                for (int j = 0; j < 4; j++) acc[r][j] += av * bv[j];
            }
        }
#pragma unroll
        for (int r = 0; r < 4; r++)
#pragma unroll
            for (int j = 0; j < 4; j++)
                out[(ty * 4 + r) * 64 + tx * 4 + j] = acc[r][j];
        __syncthreads();
        float* tmp = in; in = out; out = tmp;
    }

    if (tid >= 64) return;

    unsigned long long a[32];
#pragma unroll
    for (int q = 0; q < 16; q++) {
        float4 v = *(const float4*)(in + tid * 64 + q * 4);
        a[2 * q]     = pack2(v.x, v.y);
        a[2 * q + 1] = pack2(v.z, v.w);
    }

    float e0 = g_esum[tid];
    float e1 = g_esum[64 + tid];
    float h = 0.f;
    hb[0][tid] = 0.f;
    BAR64();

    for (int c = 0; c < NCHUNK; c++) {
        g_hstart[c * 64 + tid] = h;
        float en = (c + 2 < NCHUNK) ? __ldg(g_esum + (c + 2) * 64 + tid) : 0.f;
        const unsigned long long* hp = (const unsigned long long*)hb[c & 1];
        unsigned long long acc0 = 0, acc1 = 0, acc2 = 0, acc3 = 0;
#pragma unroll
        for (int q = 0; q < 8; q++) {
            fma2(acc0, a[4 * q + 0], hp[4 * q + 0]);
            fma2(acc1, a[4 * q + 1], hp[4 * q + 1]);
            fma2(acc2, a[4 * q + 2], hp[4 * q + 2]);
            fma2(acc3, a[4 * q + 3], hp[4 * q + 3]);
        }
        float2 f = unpk(add2(add2(acc0, acc1), add2(acc2, acc3)));
        h = f.x + f.y + e0;
        e0 = e1; e1 = en;
        hb[(c + 1) & 1][tid] = h;
        BAR64();
    }
}

// ---------------- 4c) pass C: local scans with correct h0, write H ----------------
__global__ __launch_bounds__(256) void scan_passC()
{
    __shared__ __align__(16) float u_s[64 * 64];
    __shared__ __align__(16) float hb[2][64];
    int tid = threadIdx.x, c = blockIdx.x;

    for (int f = tid; f < 1024; f += 256)
        ((float4*)u_s)[f] = ((const float4*)(g_Ut + c * 4096))[f];
    if (tid < 64) hb[0][tid] = g_hstart[c * 64 + tid];
    __syncthreads();
    if (tid >= 64) return;

    unsigned long long a[32];
    const float4* rowp = (const float4*)(g_dA + tid * 64);
#pragma unroll
    for (int q = 0; q < 16; q++) {
        float4 v = rowp[q];
        a[2 * q]     = pack2(v.x, v.y);
        a[2 * q + 1] = pack2(v.z, v.w);
    }

    for (int j = 0; j < TCH; j++) {
        const unsigned long long* hp = (const unsigned long long*)hb[j & 1];
        unsigned long long acc0 = 0, acc1 = 0, acc2 = 0, acc3 = 0;
#pragma unroll
        for (int q = 0; q < 8; q++) {
            fma2(acc0, a[4 * q + 0], hp[4 * q + 0]);
            fma2(acc1, a[4 * q + 1], hp[4 * q + 1]);
            fma2(acc2, a[4 * q + 2], hp[4 * q + 2]);
            fma2(acc3, a[4 * q + 3], hp[4 * q + 3]);
        }
        float2 f = unpk(add2(add2(acc0, acc1), add2(acc2, acc3)));
        float h = f.x + f.y + u_s[j * 64 + tid];
        u_s[j * 64 + tid] = h;
        hb[(j + 1) & 1][tid] = h;
        BAR64();
    }

    float4* dst = (float4*)(g_Ht + c * 4096);
#pragma unroll
    for (int q = 0; q < 16; q++)
        dst[q * 64 + tid] = ((const float4*)u_s)[q * 64 + tid];
}

// ---------------- 5) GEMM2 via mma.sync bf16x3: Y = C @ H + Dp * X ----------------
// CTA: 128 d x 128 t, K=64 single stage. C [d][k] = natural A (row-major),
// H [t][k] = natural B (col-major n x k). Grid (64 t, 16 d) = 1024 CTAs.
#define G2STRIDE 144
#define OFF_CH2  0
#define OFF_CL2  18432
#define OFF_HH2  36864
#define OFF_HL2  55296
#define G2_SMEM  73728

__global__ __launch_bounds__(256) void gemm2_mma(const float* __restrict__ X,
                                                 const float* __restrict__ Dp,
                                                 float* __restrict__ Y)
{
    extern __shared__ __align__(1024) char smem[];
    uint32_t sb = smem_u32(smem);
    int tid = threadIdx.x, lane = tid & 31, wid = tid >> 5;
    int t0 = blockIdx.x * 128, d0 = blockIdx.y * 128;
    int mw = wid & 3;        // d quarter (32 d)
    int nw = wid >> 2;       // t half (64 t)

    // load all four tiles (128 rows x 64 k each)
#pragma unroll
    for (int f = tid; f < 1024; f += 256) {
        int row = f >> 3, c = f & 7;
        uint32_t doff = row * G2STRIDE + c * 16;
        cpa16(sb + OFF_CH2 + doff, (const char*)g_Chi + ((size_t)(d0 + row) * 64 + c * 8) * 2);
        cpa16(sb + OFF_CL2 + doff, (const char*)g_Clo + ((size_t)(d0 + row) * 64 + c * 8) * 2);
        cpa16(sb + OFF_HH2 + doff, (const char*)g_Hthi + ((size_t)(t0 + row) * 64 + c * 8) * 2);
        cpa16(sb + OFF_HL2 + doff, (const char*)g_Htlo + ((size_t)(t0 + row) * 64 + c * 8) * 2);
    }
    CPA_COMMIT();
    CPA_WAIT0();
    __syncthreads();

    // A fragment (row-major, non-trans ldmatrix):
    //   lanes 0-7: rows 0-7 k0 | 8-15: rows 8-15 k0 | 16-23: rows 0-7 k8 | 24-31: rows 8-15 k8
    int a_drow = mw * 32 + (lane & 15);
    int a_kcol = (lane >> 4) << 3;
    // B fragment (proven gemm1 mapping)
    int b_trow = nw * 64 + ((lane >> 4) << 3) + (lane & 7);
    int b_kcol = lane & 8;

    float acc[2][8][4];
#pragma unroll
    for (int mt = 0; mt < 2; mt++)
#pragma unroll
        for (int nt = 0; nt < 8; nt++)
#pragma unroll
            for (int q = 0; q < 4; q++) acc[mt][nt][q] = 0.f;

    uint32_t ch = sb + OFF_CH2, cl = sb + OFF_CL2;
    uint32_t hh = sb + OFF_HH2, hl = sb + OFF_HL2;

#pragma unroll
    for (int s = 0; s < 4; s++) {
        int ks = s * 16;
        uint32_t aH[2][4], aL[2][4], bH[4][4], bL[4][4];
#pragma unroll
        for (int mt = 0; mt < 2; mt++) {
            uint32_t ao = (uint32_t)(a_drow + mt * 16) * G2STRIDE + (ks + a_kcol) * 2;
            ldsm_x4(aH[mt], ch + ao);
            ldsm_x4(aL[mt], cl + ao);
        }
#pragma unroll
        for (int p = 0; p < 4; p++) {
            uint32_t bo = (uint32_t)(b_trow + p * 16) * G2STRIDE + (ks + b_kcol) * 2;
            ldsm_x4(bH[p], hh + bo);
            ldsm_x4(bL[p], hl + bo);
        }
#pragma unroll
        for (int mt = 0; mt < 2; mt++)
#pragma unroll
            for (int nt = 0; nt < 8; nt++) {
                const uint32_t* bhp = &bH[nt >> 1][(nt & 1) * 2];
                const uint32_t* blp = &bL[nt >> 1][(nt & 1) * 2];
                mma16816(acc[mt][nt], aH[mt], bhp);
                mma16816(acc[mt][nt], aH[mt], blp);
                mma16816(acc[mt][nt], aL[mt], bhp);
            }
    }

    // epilogue with skip connection
#pragma unroll
    for (int mt = 0; mt < 2; mt++) {
        int d = d0 + mw * 32 + mt * 16 + (lane >> 2);
        float dp0 = Dp[d], dp1 = Dp[d + 8];
#pragma unroll
        for (int nt = 0; nt < 8; nt++) {
            int t = t0 + nw * 64 + nt * 8 + (lane & 3) * 2;
            float2 x0 = *(const float2*)(X + (size_t)d * LSEQ + t);
            float2 x1 = *(const float2*)(X + (size_t)(d + 8) * LSEQ + t);
            *(float2*)(Y + (size_t)d * LSEQ + t) =
                make_float2(acc[mt][nt][0] + dp0 * x0.x, acc[mt][nt][1] + dp0 * x0.y);
            *(float2*)(Y + (size_t)(d + 8) * LSEQ + t) =
                make_float2(acc[mt][nt][2] + dp1 * x1.x, acc[mt][nt][3] + dp1 * x1.y);
        }
    }
}

// ---------------- launch ----------------
extern "C" void kernel_launch(void* const* d_in, const int* in_sizes, int n_in,
                              void* d_out, int out_size)
{
    const float* X    = (const float*)d_in[0];   // (2048, 8192)
    const float* A    = (const float*)d_in[1];   // (64, 64)
    const float* B    = (const float*)d_in[2];   // (64, 2048)
    const float* C    = (const float*)d_in[3];   // (2048, 64)
    const float* Dp   = (const float*)d_in[4];   // (2048,)
    const float* logd = (const float*)d_in[5];   // (1,)
    float* Y = (float*)d_out;                    // (2048, 8192)

    cudaFuncSetAttribute(gemm1_mma, cudaFuncAttributeMaxDynamicSharedMemorySize, G1_SMEM);
    cudaFuncSetAttribute(gemm2_mma, cudaFuncAttributeMaxDynamicSharedMemorySize, G2_SMEM);

    prep_kernel<<<1, 256>>>(A, logd);
    dB_kernel<<<32, 256>>>(B);
    csplit_kernel<<<128, 256>>>(C);
    xsplit_kernel<<<8192, 256>>>(X);
    gemm1_mma<<<dim3(64, 2), 256, G1_SMEM>>>();
    g1reduce_kernel<<<512, 256>>>();
    scan_passA<<<NCHUNK, 256>>>();
    scan_passB<<<1, 256>>>();
    scan_passC<<<NCHUNK, 256>>>();
    hsplit_kernel<<<512, 256>>>();
    gemm2_mma<<<dim3(LSEQ / 128, D_CH / 128), 256, G2_SMEM>>>(X, Dp, Y);
}